// round 4
// baseline (speedup 1.0000x reference)
#include <cuda_runtime.h>
#include <cstdint>

// CombineEmbeddings: out[b,s,:] = (idx[b,s] >= 0) ? patch[b, idx[b,s], :]
//                                                 : word[b, s, :]
// Shapes (fixed): B=4, S=4096, P=2048, H=4096, fp32.
//
// R4: fast path = 8 contiguous cudaMemcpyAsync D2D (driver copy path),
// assuming the structural index layout (s<P -> idx==s, s>=P -> idx<0).
// A fixup kernel then validates every index against that assumption and
// re-copies any row where it fails, so the result is correct for ANY
// index contents. When the assumption holds the fixup only reads idx.

#define CE_B 4
#define CE_S 4096
#define CE_P 2048
#define CE_H 4096

__global__ void __launch_bounds__(256)
fixup_kernel(const float* __restrict__ word,
             const float* __restrict__ patch,
             const int*   __restrict__ idx,
             float*       __restrict__ out)
{
    const int row = blockIdx.x * blockDim.x + threadIdx.x;  // 0 .. B*S-1
    if (row >= CE_B * CE_S) return;

    const int b = row >> 12;          // row / S
    const int s = row & (CE_S - 1);   // row % S
    const int i = __ldg(idx + row);

    // What the memcpy fast path assumed for this row:
    //   s <  P : source was patch[b, s]
    //   s >= P : source was word[b, s]
    // Actual requirement:
    //   i >= 0 : source must be patch[b, i]
    //   i <  0 : source must be word[b, s]
    const bool assumed_patch = (s < CE_P);
    const bool mismatch = assumed_patch ? (i != s) : (i >= 0);
    if (!mismatch) return;

    const float4* __restrict__ src = (const float4*)(
        (i >= 0) ? (patch + ((int64_t)b * CE_P + i) * CE_H)
                 : (word  + (int64_t)row * CE_H));
    float4* __restrict__ dst = (float4*)(out + (int64_t)row * CE_H);

    #pragma unroll 4
    for (int k = 0; k < CE_H / 4; k++)
        dst[k] = src[k];
}

extern "C" void kernel_launch(void* const* d_in, const int* in_sizes, int n_in,
                              void* d_out, int out_size)
{
    const float* word  = (const float*)d_in[0];   // [B, S, H] fp32
    const float* patch = (const float*)d_in[1];   // [B, P, H] fp32
    const int*   idx   = (const int*)d_in[2];     // [B, S] int32
    float*       out   = (float*)d_out;           // [B, S, H] fp32

    const size_t rowBytes   = (size_t)CE_H * sizeof(float);
    const size_t patchBytes = (size_t)CE_P * rowBytes;            // 32 MiB
    const size_t tailBytes  = (size_t)(CE_S - CE_P) * rowBytes;   // 32 MiB

    for (int b = 0; b < CE_B; b++) {
        float*       outB  = out   + (int64_t)b * CE_S * CE_H;
        const float* patB  = patch + (int64_t)b * CE_P * CE_H;
        const float* wordB = word  + (int64_t)b * CE_S * CE_H;

        // out[b, 0:P, :]  <- patch[b, :, :]
        cudaMemcpyAsync(outB, patB, patchBytes, cudaMemcpyDeviceToDevice);
        // out[b, P:S, :] <- word[b, P:S, :]
        cudaMemcpyAsync(outB + (int64_t)CE_P * CE_H,
                        wordB + (int64_t)CE_P * CE_H,
                        tailBytes, cudaMemcpyDeviceToDevice);
    }

    // Validate assumption against the real indices; re-copy any mismatched
    // row. Ordered after the memcpys (same stream).
    const int rows = CE_B * CE_S;                 // 16384
    fixup_kernel<<<rows / 256, 256>>>(word, patch, idx, out);
}

// round 5
// speedup vs baseline: 1.2187x; 1.2187x over previous
#include <cuda_runtime.h>
#include <cstdint>

// CombineEmbeddings: out[b,s,:] = (idx[b,s] >= 0) ? patch[b, idx[b,s], :]
//                                                 : word[b, s, :]
// Shapes (fixed for this problem): B=4, S=4096, P=2048, H=4096, fp32.
//
// FINAL (revert to R1): pure HBM-bound row copy, 256 MiB read + 256 MiB
// write = the traffic floor. Measured 6.38 TB/s (~80% of spec), which four
// independent implementations (float4, 256-bit LDG/STG, 2-row deep-MLP with
// streaming hints, driver memcpy) all confirmed as this part's ceiling for
// a 1:1 read/write streaming mix. One CTA per 16 KB row, 256 threads,
// 4 front-batched float4 loads -> 4 stores, uniform per-CTA source select.

#define CE_B 4
#define CE_S 4096
#define CE_P 2048
#define CE_H 4096

__global__ void __launch_bounds__(256)
combine_embeddings_kernel(const float4* __restrict__ word,
                          const float4* __restrict__ patch,
                          const int*    __restrict__ idx,
                          float4*       __restrict__ out)
{
    constexpr int H4 = CE_H / 4;             // 1024 float4 per row
    const int row = blockIdx.x;              // 0 .. B*S-1
    const int b   = row >> 12;               // row / S  (S = 4096)
    const int i   = __ldg(idx + row);

    const float4* __restrict__ src =
        (i >= 0) ? (patch + ((int64_t)b * CE_P + i) * H4)
                 : (word  + (int64_t)row * H4);
    float4* __restrict__ dst = out + (int64_t)row * H4;

    // 1024 float4 / 256 threads = 4 iterations, fully unrolled:
    // all 4 loads issued before any store dependency binds.
    const int t = threadIdx.x;
    float4 v0 = src[t];
    float4 v1 = src[t + 256];
    float4 v2 = src[t + 512];
    float4 v3 = src[t + 768];
    dst[t]       = v0;
    dst[t + 256] = v1;
    dst[t + 512] = v2;
    dst[t + 768] = v3;
}

extern "C" void kernel_launch(void* const* d_in, const int* in_sizes, int n_in,
                              void* d_out, int out_size)
{
    const float4* word  = (const float4*)d_in[0];   // [B, S, H] fp32
    const float4* patch = (const float4*)d_in[1];   // [B, P, H] fp32
    const int*    idx   = (const int*)d_in[2];      // [B, S] int32
    float4*       out   = (float4*)d_out;           // [B, S, H] fp32

    const int rows = CE_B * CE_S;                   // 16384
    combine_embeddings_kernel<<<rows, 256>>>(word, patch, idx, out);
}